// round 3
// baseline (speedup 1.0000x reference)
#include <cuda_runtime.h>
#include <math.h>
#include <math_constants.h>

#define NB 2
#define LL 6400
#define SS 6400
#define CC 256
#define HH 80
#define WW 80
#define BORD 2
#define THRESH 0.2f
#define INV_SCALE (1.0f / 25.6f)   // 1/(C*temperature)

#define TM 128
#define TN 128
#define TKK 16

// ---------------- scratch (device globals: no allocation allowed) ----------
__device__ float g_sim[(size_t)NB * LL * SS];   // 327.68 MB
__device__ float g_A[NB * LL];        // log row-sum-exp
__device__ float g_B[NB * SS];        // log col-sum-exp
__device__ float g_colsum[NB * SS];
__device__ float g_Mrow[NB * LL];     // max_s (2*sim - B[s])
__device__ int   g_McolEnc[NB * SS];  // encoded max_l (2*sim - A[l])
__device__ float g_Mcol[NB * SS];

// monotonic float<->int encoding for atomicMax on floats (handles negatives)
__device__ __forceinline__ int encf(float f) {
    int i = __float_as_int(f);
    return (i >= 0) ? i : (i ^ 0x7FFFFFFF);
}
__device__ __forceinline__ float decf(int i) {
    return __int_as_float((i >= 0) ? i : (i ^ 0x7FFFFFFF));
}

__device__ __forceinline__ float blockReduceSum(float v) {
    __shared__ float sh[32];
    int lane = threadIdx.x & 31, wid = threadIdx.x >> 5;
    #pragma unroll
    for (int o = 16; o; o >>= 1) v += __shfl_down_sync(0xffffffffu, v, o);
    if (lane == 0) sh[wid] = v;
    __syncthreads();
    if (wid == 0) {
        v = (lane < (int)(blockDim.x >> 5)) ? sh[lane] : 0.0f;
        #pragma unroll
        for (int o = 16; o; o >>= 1) v += __shfl_down_sync(0xffffffffu, v, o);
    }
    return v;
}

__device__ __forceinline__ float blockReduceMax(float v) {
    __shared__ float sh[32];
    int lane = threadIdx.x & 31, wid = threadIdx.x >> 5;
    #pragma unroll
    for (int o = 16; o; o >>= 1) v = fmaxf(v, __shfl_down_sync(0xffffffffu, v, o));
    if (lane == 0) sh[wid] = v;
    __syncthreads();
    if (wid == 0) {
        v = (lane < (int)(blockDim.x >> 5)) ? sh[lane] : -CUDART_INF_F;
        #pragma unroll
        for (int o = 16; o; o >>= 1) v = fmaxf(v, __shfl_down_sync(0xffffffffu, v, o));
    }
    return v;
}

// ---------------- init ------------------------------------------------------
__global__ void cm_init_kernel() {
    int i = blockIdx.x * 256 + threadIdx.x;
    if (i < NB * SS) {
        g_colsum[i] = 0.0f;
        g_McolEnc[i] = encf(-CUDART_INF_F);
    }
}

// ---------------- GEMM: sim = x0 @ x1^T * INV_SCALE (fp32 via f32x2) --------
__global__ void __launch_bounds__(256, 2)
cm_gemm_kernel(const float* __restrict__ x0, const float* __restrict__ x1) {
    __shared__ float As[TKK][TM + 4];
    __shared__ float Bs[TKK][TN + 4];

    const int n  = blockIdx.z;
    const int m0 = blockIdx.y * TM;
    const int n0 = blockIdx.x * TN;
    const float* A = x0 + (size_t)n * LL * CC;
    const float* B = x1 + (size_t)n * SS * CC;

    const int tid = threadIdx.x;
    const int ty = tid >> 4;   // 0..15
    const int tx = tid & 15;   // 0..15

    unsigned long long acc[8][4];
    #pragma unroll
    for (int i = 0; i < 8; i++)
        #pragma unroll
        for (int j = 0; j < 4; j++) acc[i][j] = 0ULL;

    for (int k0 = 0; k0 < CC; k0 += TKK) {
        #pragma unroll
        for (int i = 0; i < 2; i++) {
            int idx = tid + i * 256;       // 0..511
            int row = idx >> 2;            // 0..127
            int kq  = (idx & 3) << 2;      // 0,4,8,12
            float4 av = *(const float4*)(A + (size_t)(m0 + row) * CC + (k0 + kq));
            As[kq + 0][row] = av.x;
            As[kq + 1][row] = av.y;
            As[kq + 2][row] = av.z;
            As[kq + 3][row] = av.w;
            float4 bv = *(const float4*)(B + (size_t)(n0 + row) * CC + (k0 + kq));
            Bs[kq + 0][row] = bv.x;
            Bs[kq + 1][row] = bv.y;
            Bs[kq + 2][row] = bv.z;
            Bs[kq + 3][row] = bv.w;
        }
        __syncthreads();
        #pragma unroll
        for (int k = 0; k < TKK; k++) {
            float4 a0 = *(const float4*)&As[k][ty * 8];
            float4 a1 = *(const float4*)&As[k][ty * 8 + 4];
            ulonglong2 bl = *(const ulonglong2*)&Bs[k][tx * 8];
            ulonglong2 bh = *(const ulonglong2*)&Bs[k][tx * 8 + 4];
            unsigned long long b2[4] = {bl.x, bl.y, bh.x, bh.y};
            float a[8] = {a0.x, a0.y, a0.z, a0.w, a1.x, a1.y, a1.z, a1.w};
            #pragma unroll
            for (int i = 0; i < 8; i++) {
                unsigned long long ad;
                asm("mov.b64 %0, {%1, %1};" : "=l"(ad) : "r"(__float_as_uint(a[i])));
                #pragma unroll
                for (int j = 0; j < 4; j++) {
                    asm("fma.rn.f32x2 %0, %1, %2, %0;"
                        : "+l"(acc[i][j]) : "l"(ad), "l"(b2[j]));
                }
            }
        }
        __syncthreads();
    }

    float* out = g_sim + (size_t)n * LL * SS;
    #pragma unroll
    for (int i = 0; i < 8; i++) {
        float o[8];
        #pragma unroll
        for (int j = 0; j < 4; j++) {
            unsigned lo = (unsigned)(acc[i][j] & 0xFFFFFFFFULL);
            unsigned hi = (unsigned)(acc[i][j] >> 32);
            o[2 * j]     = __uint_as_float(lo) * INV_SCALE;
            o[2 * j + 1] = __uint_as_float(hi) * INV_SCALE;
        }
        size_t off = (size_t)(m0 + ty * 8 + i) * SS + (n0 + tx * 8);
        *(float4*)(out + off)     = make_float4(o[0], o[1], o[2], o[3]);
        *(float4*)(out + off + 4) = make_float4(o[4], o[5], o[6], o[7]);
    }
}

// ---------------- row log-sum-exp ------------------------------------------
__global__ void cm_rowsum_kernel() {
    int row = blockIdx.x;                       // 0 .. NB*LL-1
    const float4* p = (const float4*)(g_sim + (size_t)row * SS);
    float s = 0.0f;
    for (int i = threadIdx.x; i < SS / 4; i += 256) {
        float4 v = p[i];
        s += expf(v.x) + expf(v.y) + expf(v.z) + expf(v.w);
    }
    float tot = blockReduceSum(s);
    if (threadIdx.x == 0) g_A[row] = logf(tot);
}

// ---------------- column sum-exp (atomic partials) -------------------------
__global__ void cm_colsum_kernel() {
    int n  = blockIdx.z;
    int c  = blockIdx.x * 256 + threadIdx.x;
    int r0 = blockIdx.y * 256;
    const float* p = g_sim + (size_t)n * LL * SS + (size_t)r0 * SS + c;
    float s = 0.0f;
    #pragma unroll 8
    for (int r = 0; r < 256; r++) s += expf(p[(size_t)r * SS]);
    atomicAdd(&g_colsum[n * SS + c], s);
}

__global__ void cm_logb_kernel() {
    int i = blockIdx.x * 256 + threadIdx.x;
    if (i < NB * SS) g_B[i] = logf(g_colsum[i]);
}

// ---------------- per-row max of (2*sim - B[s]) ----------------------------
__global__ void cm_rowmax_kernel() {
    int row = blockIdx.x;
    int n = row / LL;
    const float4* p  = (const float4*)(g_sim + (size_t)row * SS);
    const float4* b4 = (const float4*)(g_B + n * SS);
    float m = -CUDART_INF_F;
    for (int i = threadIdx.x; i < SS / 4; i += 256) {
        float4 v = p[i];
        float4 b = b4[i];
        m = fmaxf(m, fmaf(2.0f, v.x, -b.x));
        m = fmaxf(m, fmaf(2.0f, v.y, -b.y));
        m = fmaxf(m, fmaf(2.0f, v.z, -b.z));
        m = fmaxf(m, fmaf(2.0f, v.w, -b.w));
    }
    float tot = blockReduceMax(m);
    if (threadIdx.x == 0) g_Mrow[row] = tot;
}

// ---------------- per-col max of (2*sim - A[l]) ----------------------------
__global__ void cm_colmax_kernel() {
    int n  = blockIdx.z;
    int c  = blockIdx.x * 256 + threadIdx.x;
    int r0 = blockIdx.y * 256;
    const float* p = g_sim + (size_t)n * LL * SS + (size_t)r0 * SS + c;
    const float* a = g_A + n * LL + r0;
    float m = -CUDART_INF_F;
    #pragma unroll 8
    for (int r = 0; r < 256; r++)
        m = fmaxf(m, fmaf(2.0f, p[(size_t)r * SS], -a[r]));
    atomicMax(&g_McolEnc[n * SS + c], encf(m));
}

__global__ void cm_dec_kernel() {
    int i = blockIdx.x * 256 + threadIdx.x;
    if (i < NB * SS) g_Mcol[i] = decf(g_McolEnc[i]);
}

// ---------------- final: confidence, mask, scores --------------------------
__global__ void cm_final_kernel(float* __restrict__ out) {
    const size_t NLS = (size_t)NB * LL * SS;
    int row = blockIdx.x;                 // 0 .. NB*LL-1
    int n = row / LL;
    int l = row - n * LL;
    int ih = l / WW, iw = l - ih * WW;
    bool lvalid = (ih >= BORD) && (ih < HH - BORD) && (iw >= BORD) && (iw < WW - BORD);
    float Av = g_A[row];
    float Mr = g_Mrow[row];
    const float* p  = g_sim + (size_t)row * SS;
    const float* Bp = g_B   + n * SS;
    const float* Mc = g_Mcol + n * SS;
    float* conf_out = out + (size_t)row * SS;
    float* mask_out = out + NLS + (size_t)row * SS;
    float* scor_out = out + 2 * NLS + (size_t)row * SS;

    for (int i4 = threadIdx.x; i4 < SS / 4; i4 += 256) {
        int s = i4 * 4;
        float4 sv = *(const float4*)(p + s);
        float vv[4] = {sv.x, sv.y, sv.z, sv.w};
        float co[4], mo[4], so[4];
        #pragma unroll
        for (int j = 0; j < 4; j++) {
            int sc = s + j;
            int sh = sc / WW, sw = sc - sh * WW;
            bool svalid = (sh >= BORD) && (sh < HH - BORD) && (sw >= BORD) && (sw < WW - BORD);
            float Bv = Bp[sc];
            float t  = fmaf(2.0f, vv[j], -Bv);   // identical expr to rowmax pass
            float u  = fmaf(2.0f, vv[j], -Av);   // identical expr to colmax pass
            float cf = expf(t - Av);             // conf = exp(2*sim - A - B)
            bool mk = (cf > THRESH) && lvalid && svalid &&
                      (t == Mr) && (u == Mc[sc]);
            co[j] = cf;
            mo[j] = mk ? 1.0f : 0.0f;
            so[j] = mk ? cf : 0.0f;
        }
        *(float4*)(conf_out + s) = make_float4(co[0], co[1], co[2], co[3]);
        *(float4*)(mask_out + s) = make_float4(mo[0], mo[1], mo[2], mo[3]);
        *(float4*)(scor_out + s) = make_float4(so[0], so[1], so[2], so[3]);
    }
}

// ---------------- launch ----------------------------------------------------
extern "C" void kernel_launch(void* const* d_in, const int* in_sizes, int n_in,
                              void* d_out, int out_size) {
    const float* x0 = (const float*)d_in[0];
    const float* x1 = (const float*)d_in[1];
    float* out = (float*)d_out;

    cm_init_kernel<<<(NB * SS + 255) / 256, 256>>>();

    dim3 gg(SS / TN, LL / TM, NB);              // 50 x 50 x 2
    cm_gemm_kernel<<<gg, 256>>>(x0, x1);

    cm_rowsum_kernel<<<NB * LL, 256>>>();

    dim3 gc(SS / 256, LL / 256, NB);            // 25 x 25 x 2
    cm_colsum_kernel<<<gc, 256>>>();

    cm_logb_kernel<<<(NB * SS + 255) / 256, 256>>>();

    cm_rowmax_kernel<<<NB * LL, 256>>>();
    cm_colmax_kernel<<<gc, 256>>>();
    cm_dec_kernel<<<(NB * SS + 255) / 256, 256>>>();

    cm_final_kernel<<<NB * LL, 256>>>(out);
}

// round 6
// speedup vs baseline: 1.7072x; 1.7072x over previous
#include <cuda_runtime.h>
#include <cuda_fp16.h>
#include <math.h>
#include <math_constants.h>
#include <stdint.h>

#define NB 2
#define LL 6400
#define SS 6400
#define CC 256
#define HH 80
#define WW 80
#define BORD 2
#define THRESH 0.2f
#define INV_SCALE (1.0f / 25.6f)   // 1/(C*temperature)

// ---- GEMM tiling (mma.sync m16n8k16, fp16x3 split) ----
#define BM 128
#define BN 128
#define BKH 32                 // K halves per stage
#define NIT (CC / BKH)         // 8
#define LDS_ROW 40             // halves per smem row (32 data + 8 pad) -> 80B stride
#define TILE_B (BM * LDS_ROW * 2)     // 10240 bytes per tile
#define ST_STRIDE (4 * TILE_B)        // Ah|Al|Bh|Bl per stage = 40960
#define NSTAGE 3
#define SMEM_TOTAL (NSTAGE * ST_STRIDE)   // 122880
#define AH_O 0
#define AL_O TILE_B
#define BH_O (2 * TILE_B)
#define BL_O (3 * TILE_B)

// ---- scratch (device globals; no runtime allocation allowed) ----
__device__ float  g_sim[(size_t)NB * LL * SS];      // 327.68 MB
__device__ __half g_x0h[(size_t)NB * LL * CC];
__device__ __half g_x0l[(size_t)NB * LL * CC];
__device__ __half g_x1h[(size_t)NB * SS * CC];
__device__ __half g_x1l[(size_t)NB * SS * CC];
__device__ float  g_rowsum[NB * LL];
__device__ float  g_colsum[NB * SS];
__device__ float  g_A[NB * LL];
__device__ float  g_B[NB * SS];
__device__ int    g_McolEnc[NB * SS];
__device__ float  g_Mcol[NB * SS];

// ======================= helpers ===========================================
__device__ __forceinline__ uint32_t smem_u32(const void* p) {
    uint32_t a;
    asm("{ .reg .u64 t; cvta.to.shared.u64 t, %1; cvt.u32.u64 %0, t; }" : "=r"(a) : "l"(p));
    return a;
}
__device__ __forceinline__ void cpa16(uint32_t dst, const void* src) {
    asm volatile("cp.async.cg.shared.global [%0], [%1], 16;" :: "r"(dst), "l"(src));
}
__device__ __forceinline__ void ldsm_x4(uint32_t* r, uint32_t a) {
    asm volatile("ldmatrix.sync.aligned.m8n8.x4.shared.b16 {%0,%1,%2,%3}, [%4];"
                 : "=r"(r[0]), "=r"(r[1]), "=r"(r[2]), "=r"(r[3]) : "r"(a));
}
__device__ __forceinline__ void ldsm_x2(uint32_t* r, uint32_t a) {
    asm volatile("ldmatrix.sync.aligned.m8n8.x2.shared.b16 {%0,%1}, [%2];"
                 : "=r"(r[0]), "=r"(r[1]) : "r"(a));
}
__device__ __forceinline__ void mma168(float* c, const uint32_t* a, const uint32_t* b) {
    asm volatile(
        "mma.sync.aligned.m16n8k16.row.col.f32.f16.f16.f32 "
        "{%0,%1,%2,%3}, {%4,%5,%6,%7}, {%8,%9}, {%0,%1,%2,%3};"
        : "+f"(c[0]), "+f"(c[1]), "+f"(c[2]), "+f"(c[3])
        : "r"(a[0]), "r"(a[1]), "r"(a[2]), "r"(a[3]), "r"(b[0]), "r"(b[1]));
}

// monotonic float<->int encoding for atomicMax on floats
__device__ __forceinline__ int encf(float f) {
    int i = __float_as_int(f);
    return (i >= 0) ? i : (i ^ 0x7FFFFFFF);
}
__device__ __forceinline__ float decf(int i) {
    return __int_as_float((i >= 0) ? i : (i ^ 0x7FFFFFFF));
}

__device__ __forceinline__ float blockReduceMax(float v) {
    __shared__ float sh[32];
    int lane = threadIdx.x & 31, wid = threadIdx.x >> 5;
    #pragma unroll
    for (int o = 16; o; o >>= 1) v = fmaxf(v, __shfl_down_sync(0xffffffffu, v, o));
    if (lane == 0) sh[wid] = v;
    __syncthreads();
    if (wid == 0) {
        v = (lane < (int)(blockDim.x >> 5)) ? sh[lane] : -CUDART_INF_F;
        #pragma unroll
        for (int o = 16; o; o >>= 1) v = fmaxf(v, __shfl_down_sync(0xffffffffu, v, o));
    }
    return v;
}

// ======================= kernels ===========================================

// ---- split fp32 -> fp16 hi + fp16 lo (~22-bit combined precision) ----
__global__ void cm_split_kernel(const float* __restrict__ x0, const float* __restrict__ x1) {
    size_t i = (size_t)blockIdx.x * 256 + threadIdx.x;   // float4 index
    const size_t NV = (size_t)NB * LL * CC / 4;
    if (i >= NV) return;
    float4 a = ((const float4*)x0)[i];
    float4 b = ((const float4*)x1)[i];
    __half ah[4], al[4], bh[4], bl[4];
    float av[4] = {a.x, a.y, a.z, a.w};
    float bv[4] = {b.x, b.y, b.z, b.w};
    #pragma unroll
    for (int j = 0; j < 4; j++) {
        ah[j] = __float2half_rn(av[j]);
        al[j] = __float2half_rn(av[j] - __half2float(ah[j]));
        bh[j] = __float2half_rn(bv[j]);
        bl[j] = __float2half_rn(bv[j] - __half2float(bh[j]));
    }
    __half2* p;
    p = (__half2*)g_x0h; p[2*i] = __halves2half2(ah[0], ah[1]); p[2*i+1] = __halves2half2(ah[2], ah[3]);
    p = (__half2*)g_x0l; p[2*i] = __halves2half2(al[0], al[1]); p[2*i+1] = __halves2half2(al[2], al[3]);
    p = (__half2*)g_x1h; p[2*i] = __halves2half2(bh[0], bh[1]); p[2*i+1] = __halves2half2(bh[2], bh[3]);
    p = (__half2*)g_x1l; p[2*i] = __halves2half2(bl[0], bl[1]); p[2*i+1] = __halves2half2(bl[2], bl[3]);
}

// ---- init accumulators ----
__global__ void cm_init_kernel() {
    int i = blockIdx.x * 256 + threadIdx.x;
    if (i < NB * LL) g_rowsum[i] = 0.0f;
    if (i < NB * SS) { g_colsum[i] = 0.0f; g_McolEnc[i] = encf(-CUDART_INF_F); }
}

// ---- stage loader: Ah|Al|Bh|Bl tiles, 2048 x 16B cp.async per stage -------
__device__ __forceinline__ void load_stage(uint32_t stb, int n, int m0, int n0,
                                           int k0, int tid) {
    const size_t abase = (size_t)(n * LL + m0) * CC + k0;
    const size_t bbase = (size_t)(n * SS + n0) * CC + k0;
    #pragma unroll
    for (int i = 0; i < 8; i++) {
        int idx = tid + i * 256;          // 0..2047
        int t   = idx >> 9;               // tile 0..3
        int v   = idx & 511;
        int row = v >> 2;                 // 0..127
        int c   = v & 3;                  // 16B chunk
        const __half* g;
        if      (t == 0) g = g_x0h + abase + (size_t)row * CC;
        else if (t == 1) g = g_x0l + abase + (size_t)row * CC;
        else if (t == 2) g = g_x1h + bbase + (size_t)row * CC;
        else             g = g_x1l + bbase + (size_t)row * CC;
        uint32_t dst = stb + (uint32_t)t * TILE_B + (uint32_t)row * (LDS_ROW * 2) + c * 16;
        cpa16(dst, g + c * 8);
    }
}

// ---- GEMM: sim = (x0 @ x1^T) * INV_SCALE via fp16x3 mma.sync --------------
__global__ void __launch_bounds__(256, 1)
cm_gemm_hmma() {
    extern __shared__ char sm[];
    uint32_t sb = smem_u32(sm);
    const int tid = threadIdx.x, lane = tid & 31, wid = tid >> 5;
    const int wm = wid & 1;           // 0..1 : 64-row half
    const int wn = wid >> 1;          // 0..3 : 32-col quarter
    const int n  = blockIdx.z;
    const int m0 = blockIdx.y * BM;
    const int n0 = blockIdx.x * BN;

    float cacc[4][4][4];
    #pragma unroll
    for (int fm = 0; fm < 4; fm++)
        #pragma unroll
        for (int fn = 0; fn < 4; fn++)
            #pragma unroll
            for (int q = 0; q < 4; q++) cacc[fm][fn][q] = 0.0f;

    // prologue: stages 0 and 1
    load_stage(sb + 0 * ST_STRIDE, n, m0, n0, 0,   tid);
    asm volatile("cp.async.commit_group;");
    load_stage(sb + 1 * ST_STRIDE, n, m0, n0, BKH, tid);
    asm volatile("cp.async.commit_group;");

    // precomputed intra-tile ldmatrix offsets
    const uint32_t a_row = (uint32_t)((lane & 15) * (LDS_ROW * 2));
    const uint32_t a_kof = (lane & 16) ? 16u : 0u;     // +8 halves
    const uint32_t b_row = (uint32_t)((lane & 7) * (LDS_ROW * 2));
    const uint32_t b_kof = (lane & 8) ? 16u : 0u;

    for (int it = 0; it < NIT; it++) {
        if (it + 2 < NIT) {
            load_stage(sb + ((it + 2) % NSTAGE) * ST_STRIDE, n, m0, n0, (it + 2) * BKH, tid);
            asm volatile("cp.async.commit_group;");
        }
        if (it <= NIT - 3)      asm volatile("cp.async.wait_group 2;");
        else if (it == NIT - 2) asm volatile("cp.async.wait_group 1;");
        else                    asm volatile("cp.async.wait_group 0;");
        __syncthreads();

        uint32_t st = sb + (it % NSTAGE) * ST_STRIDE;
        #pragma unroll
        for (int ks = 0; ks < 2; ks++) {
            uint32_t kbyte = (uint32_t)(ks * 32);   // 16 halves
            uint32_t ah[4][4], al[4][4];
            #pragma unroll
            for (int fm = 0; fm < 4; fm++) {
                uint32_t off = (uint32_t)((wm * 64 + fm * 16) * (LDS_ROW * 2)) + a_row + kbyte + a_kof;
                ldsm_x4(ah[fm], st + AH_O + off);
                ldsm_x4(al[fm], st + AL_O + off);
            }
            uint32_t bh[4][2], bl[4][2];
            #pragma unroll
            for (int fn = 0; fn < 4; fn++) {
                uint32_t off = (uint32_t)((wn * 32 + fn * 8) * (LDS_ROW * 2)) + b_row + kbyte + b_kof;
                ldsm_x2(bh[fn], st + BH_O + off);
                ldsm_x2(bl[fn], st + BL_O + off);
            }
            #pragma unroll
            for (int fm = 0; fm < 4; fm++)
                #pragma unroll
                for (int fn = 0; fn < 4; fn++) {
                    mma168(cacc[fm][fn], ah[fm], bh[fn]);
                    mma168(cacc[fm][fn], ah[fm], bl[fn]);
                    mma168(cacc[fm][fn], al[fm], bh[fn]);
                }
        }
        __syncthreads();
    }

    // epilogue
    float* outb = g_sim + (size_t)n * LL * SS;
    #pragma unroll
    for (int fm = 0; fm < 4; fm++) {
        int r = m0 + wm * 64 + fm * 16 + (lane >> 2);
        #pragma unroll
        for (int fn = 0; fn < 4; fn++) {
            int cc0 = n0 + wn * 32 + fn * 8 + (lane & 3) * 2;
            float2 v0 = make_float2(cacc[fm][fn][0] * INV_SCALE, cacc[fm][fn][1] * INV_SCALE);
            float2 v1 = make_float2(cacc[fm][fn][2] * INV_SCALE, cacc[fm][fn][3] * INV_SCALE);
            *(float2*)(outb + (size_t)r * SS + cc0)       = v0;
            *(float2*)(outb + (size_t)(r + 8) * SS + cc0) = v1;
        }
    }
}

// ---- fused row-sum-exp + col-sum-exp (one read of sim) --------------------
__global__ void __launch_bounds__(256) cm_sums_kernel() {
    int n  = blockIdx.z;
    int c0 = blockIdx.x * 256;
    int r0 = blockIdx.y * 256;
    int tid = threadIdx.x, wid = tid >> 5, lid = tid & 31;
    __shared__ float csum[256];
    csum[tid] = 0.0f;
    __syncthreads();
    const float* base = g_sim + (size_t)n * LL * SS;
    float acc[8] = {0, 0, 0, 0, 0, 0, 0, 0};
    for (int i = 0; i < 32; i++) {
        int r = r0 + wid + i * 8;
        const float4* p = (const float4*)(base + (size_t)r * SS + c0);
        float4 v0 = p[lid];
        float4 v1 = p[32 + lid];
        float e0 = expf(v0.x), e1 = expf(v0.y), e2 = expf(v0.z), e3 = expf(v0.w);
        float e4 = expf(v1.x), e5 = expf(v1.y), e6 = expf(v1.z), e7 = expf(v1.w);
        acc[0] += e0; acc[1] += e1; acc[2] += e2; acc[3] += e3;
        acc[4] += e4; acc[5] += e5; acc[6] += e6; acc[7] += e7;
        float rs = ((e0 + e1) + (e2 + e3)) + ((e4 + e5) + (e6 + e7));
        #pragma unroll
        for (int o = 16; o; o >>= 1) rs += __shfl_down_sync(0xffffffffu, rs, o);
        if (lid == 0) atomicAdd(&g_rowsum[n * LL + r], rs);
    }
    #pragma unroll
    for (int k = 0; k < 4; k++) {
        atomicAdd(&csum[lid * 4 + k], acc[k]);
        atomicAdd(&csum[128 + lid * 4 + k], acc[4 + k]);
    }
    __syncthreads();
    atomicAdd(&g_colsum[n * SS + c0 + tid], csum[tid]);
}

__global__ void cm_logab_kernel() {
    int i = blockIdx.x * 256 + threadIdx.x;
    if (i < NB * LL) g_A[i] = logf(g_rowsum[i]);
    if (i < NB * SS) g_B[i] = logf(g_colsum[i]);
}

// ---- per-col max of (2*sim - A[l]) ----------------------------------------
__global__ void __launch_bounds__(256) cm_colmax_kernel() {
    int n  = blockIdx.z;
    int c0 = blockIdx.x * 256;
    int r0 = blockIdx.y * 256;
    int tid = threadIdx.x, wid = tid >> 5, lid = tid & 31;
    __shared__ int cmx[256];
    cmx[tid] = encf(-CUDART_INF_F);
    __syncthreads();
    const float* base = g_sim + (size_t)n * LL * SS;
    const float* Ab = g_A + n * LL;
    float acc[8];
    #pragma unroll
    for (int k = 0; k < 8; k++) acc[k] = -CUDART_INF_F;
    for (int i = 0; i < 32; i++) {
        int r = r0 + wid + i * 8;
        float Ar = Ab[r];
        const float4* p = (const float4*)(base + (size_t)r * SS + c0);
        float4 v0 = p[lid];
        float4 v1 = p[32 + lid];
        acc[0] = fmaxf(acc[0], fmaf(2.0f, v0.x, -Ar));
        acc[1] = fmaxf(acc[1], fmaf(2.0f, v0.y, -Ar));
        acc[2] = fmaxf(acc[2], fmaf(2.0f, v0.z, -Ar));
        acc[3] = fmaxf(acc[3], fmaf(2.0f, v0.w, -Ar));
        acc[4] = fmaxf(acc[4], fmaf(2.0f, v1.x, -Ar));
        acc[5] = fmaxf(acc[5], fmaf(2.0f, v1.y, -Ar));
        acc[6] = fmaxf(acc[6], fmaf(2.0f, v1.z, -Ar));
        acc[7] = fmaxf(acc[7], fmaf(2.0f, v1.w, -Ar));
    }
    #pragma unroll
    for (int k = 0; k < 4; k++) {
        atomicMax(&cmx[lid * 4 + k], encf(acc[k]));
        atomicMax(&cmx[128 + lid * 4 + k], encf(acc[4 + k]));
    }
    __syncthreads();
    atomicMax(&g_McolEnc[n * SS + c0 + tid], cmx[tid]);
}

__global__ void cm_dec_kernel() {
    int i = blockIdx.x * 256 + threadIdx.x;
    if (i < NB * SS) g_Mcol[i] = decf(g_McolEnc[i]);
}

// ---- final: inline row-max of t, then confidence/mask/scores --------------
__global__ void __launch_bounds__(256) cm_final_kernel(float* __restrict__ out) {
    const size_t NLS = (size_t)NB * LL * SS;
    int row = blockIdx.x;
    int n = row / LL;
    int l = row - n * LL;
    int ih = l / WW, iw = l - ih * WW;
    bool lvalid = (ih >= BORD) && (ih < HH - BORD) && (iw >= BORD) && (iw < WW - BORD);
    float Av = g_A[row];
    const float* p  = g_sim + (size_t)row * SS;
    const float* Bp = g_B + n * SS;
    const float* Mc = g_Mcol + n * SS;
    float* conf_out = out + (size_t)row * SS;
    float* mask_out = out + NLS + (size_t)row * SS;
    float* scor_out = out + 2 * NLS + (size_t)row * SS;

    // pass 1: row max of t = fma(2, sim, -B[s])
    float m = -CUDART_INF_F;
    for (int i4 = threadIdx.x; i4 < SS / 4; i4 += 256) {
        float4 v = ((const float4*)p)[i4];
        float4 b = ((const float4*)Bp)[i4];
        m = fmaxf(m, fmaf(2.0f, v.x, -b.x));
        m = fmaxf(m, fmaf(2.0f, v.y, -b.y));
        m = fmaxf(m, fmaf(2.0f, v.z, -b.z));
        m = fmaxf(m, fmaf(2.0f, v.w, -b.w));
    }
    float mr = blockReduceMax(m);
    __shared__ float sMr;
    if (threadIdx.x == 0) sMr = mr;
    __syncthreads();
    float Mr = sMr;

    // pass 2 (row is L1-resident): outputs
    for (int i4 = threadIdx.x; i4 < SS / 4; i4 += 256) {
        int s = i4 * 4;
        float4 sv = *(const float4*)(p + s);
        float4 bv = *(const float4*)(Bp + s);
        float vv[4] = {sv.x, sv.y, sv.z, sv.w};
        float bb[4] = {bv.x, bv.y, bv.z, bv.w};
        float co[4], mo[4], so[4];
        #pragma unroll
        for (int j = 0; j < 4; j++) {
            int sc = s + j;
            int sh = sc / WW, sw = sc - sh * WW;
            bool svalid = (sh >= BORD) && (sh < HH - BORD) && (sw >= BORD) && (sw < WW - BORD);
            float t = fmaf(2.0f, vv[j], -bb[j]);   // identical expr to pass 1
            float u = fmaf(2.0f, vv[j], -Av);      // identical expr to colmax pass
            float cf = expf(t - Av);               // conf = exp(2*sim - A - B)
            bool mk = (cf > THRESH) && lvalid && svalid && (t == Mr) && (u == Mc[sc]);
            co[j] = cf;
            mo[j] = mk ? 1.0f : 0.0f;
            so[j] = mk ? cf : 0.0f;
        }
        *(float4*)(conf_out + s) = make_float4(co[0], co[1], co[2], co[3]);
        *(float4*)(mask_out + s) = make_float4(mo[0], mo[1], mo[2], mo[3]);
        *(float4*)(scor_out + s) = make_float4(so[0], so[1], so[2], so[3]);
    }
}

// ---- launch ----------------------------------------------------------------
extern "C" void kernel_launch(void* const* d_in, const int* in_sizes, int n_in,
                              void* d_out, int out_size) {
    const float* x0 = (const float*)d_in[0];
    const float* x1 = (const float*)d_in[1];
    float* out = (float*)d_out;

    cudaFuncSetAttribute(cm_gemm_hmma, cudaFuncAttributeMaxDynamicSharedMemorySize, SMEM_TOTAL);

    cm_split_kernel<<<(NB * LL * CC / 4 + 255) / 256, 256>>>(x0, x1);
    cm_init_kernel<<<(NB * SS + 255) / 256, 256>>>();

    dim3 gg(SS / BN, LL / BM, NB);      // (50, 50, 2)
    cm_gemm_hmma<<<gg, 256, SMEM_TOTAL>>>();

    dim3 gs(SS / 256, LL / 256, NB);    // (25, 25, 2)
    cm_sums_kernel<<<gs, 256>>>();
    cm_logab_kernel<<<(NB * SS + 255) / 256, 256>>>();
    cm_colmax_kernel<<<gs, 256>>>();
    cm_dec_kernel<<<(NB * SS + 255) / 256, 256>>>();

    cm_final_kernel<<<NB * LL, 256>>>(out);
}

// round 7
// speedup vs baseline: 1.7595x; 1.0306x over previous
#include <cuda_runtime.h>
#include <cuda_fp16.h>
#include <math.h>
#include <math_constants.h>
#include <stdint.h>

#define NB 2
#define LL 6400
#define SS 6400
#define CC 256
#define HH 80
#define WW 80
#define BORD 2
#define THRESH 0.2f
#define INV_SCALE (1.0f / 25.6f)   // 1/(C*temperature)

// ---- GEMM tiling (mma.sync m16n8k16, fp16x3 split) ----
#define BM 128
#define BN 128
#define BKH 32                 // K halves per stage
#define NIT (CC / BKH)         // 8
#define LDS_ROW 40             // halves per smem row (32 data + 8 pad) -> 80B stride
#define TILE_B (BM * LDS_ROW * 2)     // 10240 bytes per tile
#define ST_STRIDE (4 * TILE_B)        // Ah|Al|Bh|Bl per stage = 40960
#define NSTAGE 3
#define SMEM_TOTAL (NSTAGE * ST_STRIDE)   // 122880
#define AH_O 0
#define AL_O TILE_B
#define BH_O (2 * TILE_B)
#define BL_O (3 * TILE_B)

// ---- scratch (device globals; no runtime allocation allowed) ----
__device__ float  g_sim[(size_t)NB * LL * SS];      // 327.68 MB
__device__ __half g_x0h[(size_t)NB * LL * CC];
__device__ __half g_x0l[(size_t)NB * LL * CC];
__device__ __half g_x1h[(size_t)NB * SS * CC];
__device__ __half g_x1l[(size_t)NB * SS * CC];
__device__ float  g_rowsum[NB * LL];
__device__ float  g_colsum[NB * SS];
__device__ float  g_A[NB * LL];
__device__ float  g_B[NB * SS];
__device__ int    g_McolEnc[NB * SS];

// ======================= helpers ===========================================
__device__ __forceinline__ uint32_t smem_u32(const void* p) {
    uint32_t a;
    asm("{ .reg .u64 t; cvta.to.shared.u64 t, %1; cvt.u32.u64 %0, t; }" : "=r"(a) : "l"(p));
    return a;
}
__device__ __forceinline__ void cpa16(uint32_t dst, const void* src) {
    asm volatile("cp.async.cg.shared.global [%0], [%1], 16;" :: "r"(dst), "l"(src));
}
__device__ __forceinline__ void ldsm_x4(uint32_t* r, uint32_t a) {
    asm volatile("ldmatrix.sync.aligned.m8n8.x4.shared.b16 {%0,%1,%2,%3}, [%4];"
                 : "=r"(r[0]), "=r"(r[1]), "=r"(r[2]), "=r"(r[3]) : "r"(a));
}
__device__ __forceinline__ void ldsm_x2(uint32_t* r, uint32_t a) {
    asm volatile("ldmatrix.sync.aligned.m8n8.x2.shared.b16 {%0,%1}, [%2];"
                 : "=r"(r[0]), "=r"(r[1]) : "r"(a));
}
__device__ __forceinline__ void mma168(float* c, const uint32_t* a, const uint32_t* b) {
    asm volatile(
        "mma.sync.aligned.m16n8k16.row.col.f32.f16.f16.f32 "
        "{%0,%1,%2,%3}, {%4,%5,%6,%7}, {%8,%9}, {%0,%1,%2,%3};"
        : "+f"(c[0]), "+f"(c[1]), "+f"(c[2]), "+f"(c[3])
        : "r"(a[0]), "r"(a[1]), "r"(a[2]), "r"(a[3]), "r"(b[0]), "r"(b[1]));
}

// monotonic float<->int encoding for atomicMax on floats
__device__ __forceinline__ int encf(float f) {
    int i = __float_as_int(f);
    return (i >= 0) ? i : (i ^ 0x7FFFFFFF);
}
__device__ __forceinline__ float decf(int i) {
    return __int_as_float((i >= 0) ? i : (i ^ 0x7FFFFFFF));
}

__device__ __forceinline__ float blockReduceMax(float v) {
    __shared__ float sh[32];
    int lane = threadIdx.x & 31, wid = threadIdx.x >> 5;
    #pragma unroll
    for (int o = 16; o; o >>= 1) v = fmaxf(v, __shfl_down_sync(0xffffffffu, v, o));
    if (lane == 0) sh[wid] = v;
    __syncthreads();
    if (wid == 0) {
        v = (lane < (int)(blockDim.x >> 5)) ? sh[lane] : -CUDART_INF_F;
        #pragma unroll
        for (int o = 16; o; o >>= 1) v = fmaxf(v, __shfl_down_sync(0xffffffffu, v, o));
    }
    return v;
}

// ======================= kernels ===========================================

// ---- split fp32 -> fp16 hi + fp16 lo (~22-bit combined precision) ----
__global__ void cm_split_kernel(const float* __restrict__ x0, const float* __restrict__ x1) {
    size_t i = (size_t)blockIdx.x * 256 + threadIdx.x;   // float4 index
    const size_t NV = (size_t)NB * LL * CC / 4;
    if (i >= NV) return;
    float4 a = ((const float4*)x0)[i];
    float4 b = ((const float4*)x1)[i];
    __half ah[4], al[4], bh[4], bl[4];
    float av[4] = {a.x, a.y, a.z, a.w};
    float bv[4] = {b.x, b.y, b.z, b.w};
    #pragma unroll
    for (int j = 0; j < 4; j++) {
        ah[j] = __float2half_rn(av[j]);
        al[j] = __float2half_rn(av[j] - __half2float(ah[j]));
        bh[j] = __float2half_rn(bv[j]);
        bl[j] = __float2half_rn(bv[j] - __half2float(bh[j]));
    }
    __half2* p;
    p = (__half2*)g_x0h; p[2*i] = __halves2half2(ah[0], ah[1]); p[2*i+1] = __halves2half2(ah[2], ah[3]);
    p = (__half2*)g_x0l; p[2*i] = __halves2half2(al[0], al[1]); p[2*i+1] = __halves2half2(al[2], al[3]);
    p = (__half2*)g_x1h; p[2*i] = __halves2half2(bh[0], bh[1]); p[2*i+1] = __halves2half2(bh[2], bh[3]);
    p = (__half2*)g_x1l; p[2*i] = __halves2half2(bl[0], bl[1]); p[2*i+1] = __halves2half2(bl[2], bl[3]);
}

// ---- init accumulators ----
__global__ void cm_init_kernel() {
    int i = blockIdx.x * 256 + threadIdx.x;
    if (i < NB * LL) g_rowsum[i] = 0.0f;
    if (i < NB * SS) { g_colsum[i] = 0.0f; g_McolEnc[i] = encf(-CUDART_INF_F); }
}

// ---- stage loader: Ah|Al|Bh|Bl tiles, 2048 x 16B cp.async per stage -------
__device__ __forceinline__ void load_stage(uint32_t stb, int n, int m0, int n0,
                                           int k0, int tid) {
    const size_t abase = (size_t)(n * LL + m0) * CC + k0;
    const size_t bbase = (size_t)(n * SS + n0) * CC + k0;
    #pragma unroll
    for (int i = 0; i < 8; i++) {
        int idx = tid + i * 256;          // 0..2047
        int t   = idx >> 9;               // tile 0..3
        int v   = idx & 511;
        int row = v >> 2;                 // 0..127
        int c   = v & 3;                  // 16B chunk
        const __half* g;
        if      (t == 0) g = g_x0h + abase + (size_t)row * CC;
        else if (t == 1) g = g_x0l + abase + (size_t)row * CC;
        else if (t == 2) g = g_x1h + bbase + (size_t)row * CC;
        else             g = g_x1l + bbase + (size_t)row * CC;
        uint32_t dst = stb + (uint32_t)t * TILE_B + (uint32_t)row * (LDS_ROW * 2) + c * 16;
        cpa16(dst, g + c * 8);
    }
}

// ---- GEMM: sim = (x0 @ x1^T) * INV_SCALE via fp16x3 mma.sync,
//      with fused row/col sum-of-exp accumulation in the epilogue ----------
__global__ void __launch_bounds__(256, 1)
cm_gemm_hmma() {
    extern __shared__ char sm[];
    uint32_t sb = smem_u32(sm);
    const int tid = threadIdx.x, lane = tid & 31, wid = tid >> 5;
    const int wm = wid & 1;           // 0..1 : 64-row half
    const int wn = wid >> 1;          // 0..3 : 32-col quarter
    const int n  = blockIdx.z;
    const int m0 = blockIdx.y * BM;
    const int n0 = blockIdx.x * BN;

    float cacc[4][4][4];
    #pragma unroll
    for (int fm = 0; fm < 4; fm++)
        #pragma unroll
        for (int fn = 0; fn < 4; fn++)
            #pragma unroll
            for (int q = 0; q < 4; q++) cacc[fm][fn][q] = 0.0f;

    // prologue: stages 0 and 1
    load_stage(sb + 0 * ST_STRIDE, n, m0, n0, 0,   tid);
    asm volatile("cp.async.commit_group;");
    load_stage(sb + 1 * ST_STRIDE, n, m0, n0, BKH, tid);
    asm volatile("cp.async.commit_group;");

    const uint32_t a_row = (uint32_t)((lane & 15) * (LDS_ROW * 2));
    const uint32_t a_kof = (lane & 16) ? 16u : 0u;     // +8 halves
    const uint32_t b_row = (uint32_t)((lane & 7) * (LDS_ROW * 2));
    const uint32_t b_kof = (lane & 8) ? 16u : 0u;

    for (int it = 0; it < NIT; it++) {
        if (it + 2 < NIT) {
            load_stage(sb + ((it + 2) % NSTAGE) * ST_STRIDE, n, m0, n0, (it + 2) * BKH, tid);
            asm volatile("cp.async.commit_group;");
        }
        if (it <= NIT - 3)      asm volatile("cp.async.wait_group 2;");
        else if (it == NIT - 2) asm volatile("cp.async.wait_group 1;");
        else                    asm volatile("cp.async.wait_group 0;");
        __syncthreads();

        uint32_t st = sb + (it % NSTAGE) * ST_STRIDE;
        #pragma unroll
        for (int ks = 0; ks < 2; ks++) {
            uint32_t kbyte = (uint32_t)(ks * 32);   // 16 halves
            uint32_t ah[4][4], al[4][4];
            #pragma unroll
            for (int fm = 0; fm < 4; fm++) {
                uint32_t off = (uint32_t)((wm * 64 + fm * 16) * (LDS_ROW * 2)) + a_row + kbyte + a_kof;
                ldsm_x4(ah[fm], st + AH_O + off);
                ldsm_x4(al[fm], st + AL_O + off);
            }
            uint32_t bh[4][2], bl[4][2];
            #pragma unroll
            for (int fn = 0; fn < 4; fn++) {
                uint32_t off = (uint32_t)((wn * 32 + fn * 8) * (LDS_ROW * 2)) + b_row + kbyte + b_kof;
                ldsm_x2(bh[fn], st + BH_O + off);
                ldsm_x2(bl[fn], st + BL_O + off);
            }
            #pragma unroll
            for (int fm = 0; fm < 4; fm++)
                #pragma unroll
                for (int fn = 0; fn < 4; fn++) {
                    mma168(cacc[fm][fn], ah[fm], bh[fn]);
                    mma168(cacc[fm][fn], ah[fm], bl[fn]);
                    mma168(cacc[fm][fn], al[fm], bh[fn]);
                }
        }
        __syncthreads();
    }

    // ---- epilogue: scale + store sim, and fused exp-sum reduction ----
    float* outb = g_sim + (size_t)n * LL * SS;
    #pragma unroll
    for (int fm = 0; fm < 4; fm++) {
        int r = m0 + wm * 64 + fm * 16 + (lane >> 2);
        #pragma unroll
        for (int fn = 0; fn < 4; fn++) {
            #pragma unroll
            for (int q = 0; q < 4; q++) cacc[fm][fn][q] *= INV_SCALE;
            int cc0 = n0 + wn * 32 + fn * 8 + (lane & 3) * 2;
            *(float2*)(outb + (size_t)r * SS + cc0)       = make_float2(cacc[fm][fn][0], cacc[fm][fn][1]);
            *(float2*)(outb + (size_t)(r + 8) * SS + cc0) = make_float2(cacc[fm][fn][2], cacc[fm][fn][3]);
        }
    }

    // stage smem is dead now: alias row/col partial buffers onto it
    float* s_row = (float*)sm;          // 128 floats
    float* s_col = s_row + 128;         // 128 floats
    if (tid < 128) s_row[tid] = 0.0f; else s_col[tid - 128] = 0.0f;
    __syncthreads();

    float cp[8];
    #pragma unroll
    for (int k = 0; k < 8; k++) cp[k] = 0.0f;
    #pragma unroll
    for (int fm = 0; fm < 4; fm++) {
        float rp0 = 0.0f, rp1 = 0.0f;
        #pragma unroll
        for (int fn = 0; fn < 4; fn++) {
            float e0 = __expf(cacc[fm][fn][0]);
            float e1 = __expf(cacc[fm][fn][1]);
            float e2 = __expf(cacc[fm][fn][2]);
            float e3 = __expf(cacc[fm][fn][3]);
            rp0 += e0 + e1;
            rp1 += e2 + e3;
            cp[fn * 2]     += e0 + e2;
            cp[fn * 2 + 1] += e1 + e3;
        }
        // reduce row partials over lanes sharing the row (lane&3)
        rp0 += __shfl_xor_sync(0xffffffffu, rp0, 1);
        rp0 += __shfl_xor_sync(0xffffffffu, rp0, 2);
        rp1 += __shfl_xor_sync(0xffffffffu, rp1, 1);
        rp1 += __shfl_xor_sync(0xffffffffu, rp1, 2);
        if ((lane & 3) == 0) {
            int rl = wm * 64 + fm * 16 + (lane >> 2);
            atomicAdd(&s_row[rl], rp0);
            atomicAdd(&s_row[rl + 8], rp1);
        }
    }
    // reduce col partials over lanes sharing the col (lane>>2)
    #pragma unroll
    for (int k = 0; k < 8; k++) {
        cp[k] += __shfl_xor_sync(0xffffffffu, cp[k], 4);
        cp[k] += __shfl_xor_sync(0xffffffffu, cp[k], 8);
        cp[k] += __shfl_xor_sync(0xffffffffu, cp[k], 16);
    }
    if (lane < 4) {
        #pragma unroll
        for (int k = 0; k < 8; k++) {
            int cl = wn * 32 + (k >> 1) * 8 + lane * 2 + (k & 1);
            atomicAdd(&s_col[cl], cp[k]);
        }
    }
    __syncthreads();
    if (tid < 128) atomicAdd(&g_rowsum[n * LL + m0 + tid], s_row[tid]);
    else           atomicAdd(&g_colsum[n * SS + n0 + tid - 128], s_col[tid - 128]);
}

__global__ void cm_logab_kernel() {
    int i = blockIdx.x * 256 + threadIdx.x;
    if (i < NB * LL) g_A[i] = __logf(g_rowsum[i]);
    if (i < NB * SS) g_B[i] = __logf(g_colsum[i]);
}

// ---- per-col max of (2*sim - A[l]) ----------------------------------------
__global__ void __launch_bounds__(256) cm_colmax_kernel() {
    int n  = blockIdx.z;
    int c0 = blockIdx.x * 256;
    int r0 = blockIdx.y * 256;
    int tid = threadIdx.x, wid = tid >> 5, lid = tid & 31;
    __shared__ int cmx[256];
    cmx[tid] = encf(-CUDART_INF_F);
    __syncthreads();
    const float* base = g_sim + (size_t)n * LL * SS;
    const float* Ab = g_A + n * LL;
    float acc[8];
    #pragma unroll
    for (int k = 0; k < 8; k++) acc[k] = -CUDART_INF_F;
    for (int i = 0; i < 32; i++) {
        int r = r0 + wid + i * 8;
        float Ar = Ab[r];
        const float4* p = (const float4*)(base + (size_t)r * SS + c0);
        float4 v0 = p[lid];
        float4 v1 = p[32 + lid];
        acc[0] = fmaxf(acc[0], fmaf(2.0f, v0.x, -Ar));
        acc[1] = fmaxf(acc[1], fmaf(2.0f, v0.y, -Ar));
        acc[2] = fmaxf(acc[2], fmaf(2.0f, v0.z, -Ar));
        acc[3] = fmaxf(acc[3], fmaf(2.0f, v0.w, -Ar));
        acc[4] = fmaxf(acc[4], fmaf(2.0f, v1.x, -Ar));
        acc[5] = fmaxf(acc[5], fmaf(2.0f, v1.y, -Ar));
        acc[6] = fmaxf(acc[6], fmaf(2.0f, v1.z, -Ar));
        acc[7] = fmaxf(acc[7], fmaf(2.0f, v1.w, -Ar));
    }
    #pragma unroll
    for (int k = 0; k < 4; k++) {
        atomicMax(&cmx[lid * 4 + k], encf(acc[k]));
        atomicMax(&cmx[128 + lid * 4 + k], encf(acc[4 + k]));
    }
    __syncthreads();
    atomicMax(&g_McolEnc[n * SS + c0 + tid], cmx[tid]);
}

// ---- final: inline row-max of t, then confidence/mask/scores --------------
__global__ void __launch_bounds__(256) cm_final_kernel(float* __restrict__ out) {
    const size_t NLS = (size_t)NB * LL * SS;
    int row = blockIdx.x;
    int n = row / LL;
    int l = row - n * LL;
    int ih = l / WW, iw = l - ih * WW;
    bool lvalid = (ih >= BORD) && (ih < HH - BORD) && (iw >= BORD) && (iw < WW - BORD);
    float Av = g_A[row];
    const float* p  = g_sim + (size_t)row * SS;
    const float* Bp = g_B + n * SS;
    const int* McE  = g_McolEnc + n * SS;
    float* conf_out = out + (size_t)row * SS;
    float* mask_out = out + NLS + (size_t)row * SS;
    float* scor_out = out + 2 * NLS + (size_t)row * SS;

    // pass 1: row max of t = fma(2, sim, -B[s])
    float m = -CUDART_INF_F;
    for (int i4 = threadIdx.x; i4 < SS / 4; i4 += 256) {
        float4 v = ((const float4*)p)[i4];
        float4 b = ((const float4*)Bp)[i4];
        m = fmaxf(m, fmaf(2.0f, v.x, -b.x));
        m = fmaxf(m, fmaf(2.0f, v.y, -b.y));
        m = fmaxf(m, fmaf(2.0f, v.z, -b.z));
        m = fmaxf(m, fmaf(2.0f, v.w, -b.w));
    }
    float mr = blockReduceMax(m);
    __shared__ float sMr;
    if (threadIdx.x == 0) sMr = mr;
    __syncthreads();
    float Mr = sMr;

    // pass 2 (row is L1-resident): outputs
    for (int i4 = threadIdx.x; i4 < SS / 4; i4 += 256) {
        int s = i4 * 4;
        float4 sv = *(const float4*)(p + s);
        float4 bv = *(const float4*)(Bp + s);
        float vv[4] = {sv.x, sv.y, sv.z, sv.w};
        float bb[4] = {bv.x, bv.y, bv.z, bv.w};
        float co[4], mo[4], so[4];
        #pragma unroll
        for (int j = 0; j < 4; j++) {
            int sc = s + j;
            int sh = sc / WW, sw = sc - sh * WW;
            bool svalid = (sh >= BORD) && (sh < HH - BORD) && (sw >= BORD) && (sw < WW - BORD);
            float t = fmaf(2.0f, vv[j], -bb[j]);   // identical expr to pass 1
            float u = fmaf(2.0f, vv[j], -Av);      // identical expr to colmax pass
            float cf = __expf(t - Av);             // conf = exp(2*sim - A - B)
            bool mk = (cf > THRESH) && lvalid && svalid &&
                      (t == Mr) && (u == decf(McE[sc]));
            co[j] = cf;
            mo[j] = mk ? 1.0f : 0.0f;
            so[j] = mk ? cf : 0.0f;
        }
        *(float4*)(conf_out + s) = make_float4(co[0], co[1], co[2], co[3]);
        *(float4*)(mask_out + s) = make_float4(mo[0], mo[1], mo[2], mo[3]);
        *(float4*)(scor_out + s) = make_float4(so[0], so[1], so[2], so[3]);
    }
}

// ---- launch ----------------------------------------------------------------
extern "C" void kernel_launch(void* const* d_in, const int* in_sizes, int n_in,
                              void* d_out, int out_size) {
    const float* x0 = (const float*)d_in[0];
    const float* x1 = (const float*)d_in[1];
    float* out = (float*)d_out;

    cudaFuncSetAttribute(cm_gemm_hmma, cudaFuncAttributeMaxDynamicSharedMemorySize, SMEM_TOTAL);

    cm_split_kernel<<<(NB * LL * CC / 4 + 255) / 256, 256>>>(x0, x1);
    cm_init_kernel<<<(NB * SS + 255) / 256, 256>>>();

    dim3 gg(SS / BN, LL / BM, NB);      // (50, 50, 2)
    cm_gemm_hmma<<<gg, 256, SMEM_TOTAL>>>();

    cm_logab_kernel<<<(NB * SS + 255) / 256, 256>>>();

    dim3 gs(SS / 256, LL / 256, NB);    // (25, 25, 2)
    cm_colmax_kernel<<<gs, 256>>>();

    cm_final_kernel<<<NB * LL, 256>>>(out);
}

// round 9
// speedup vs baseline: 2.0400x; 1.1594x over previous
#include <cuda_runtime.h>
#include <cuda_fp16.h>
#include <math.h>
#include <math_constants.h>
#include <stdint.h>

#define NB 2
#define LL 6400
#define SS 6400
#define CC 256
#define HH 80
#define WW 80
#define BORD 2
#define THRESH 0.2f
#define INV_SCALE (1.0f / 25.6f)   // 1/(C*temperature)

// ---- GEMM tiling (mma.sync m16n8k16, fp16x3 split) ----
#define BM 128
#define BN 128
#define BKH 32                 // K halves per stage
#define NIT (CC / BKH)         // 8
#define LDS_ROW 40             // halves per smem row (32 data + 8 pad) -> 80B stride
#define TILE_B (BM * LDS_ROW * 2)     // 10240 bytes per tile
#define ST_STRIDE (4 * TILE_B)        // Ah|Al|Bh|Bl per stage = 40960
#define NSTAGE 2
#define SMEM_TOTAL (NSTAGE * ST_STRIDE)   // 81920 -> 2 CTAs/SM
#define AH_O 0
#define AL_O TILE_B
#define BH_O (2 * TILE_B)
#define BL_O (3 * TILE_B)

// ---- scratch (device globals; no runtime allocation allowed) ----
__device__ float  g_sim[(size_t)NB * LL * SS];      // 327.68 MB
__device__ __half g_x0h[(size_t)NB * LL * CC];
__device__ __half g_x0l[(size_t)NB * LL * CC];
__device__ __half g_x1h[(size_t)NB * SS * CC];
__device__ __half g_x1l[(size_t)NB * SS * CC];
__device__ float  g_rowsum[NB * LL];
__device__ float  g_colsum[NB * SS];
__device__ float  g_A[NB * LL];
__device__ float  g_B[NB * SS];
__device__ int    g_McolEnc[NB * SS];
__device__ int    g_MrowEnc[NB * LL];

// ======================= helpers ===========================================
__device__ __forceinline__ uint32_t smem_u32(const void* p) {
    uint32_t a;
    asm("{ .reg .u64 t; cvta.to.shared.u64 t, %1; cvt.u32.u64 %0, t; }" : "=r"(a) : "l"(p));
    return a;
}
__device__ __forceinline__ void cpa16(uint32_t dst, const void* src) {
    asm volatile("cp.async.cg.shared.global [%0], [%1], 16;" :: "r"(dst), "l"(src));
}
__device__ __forceinline__ void ldsm_x4(uint32_t* r, uint32_t a) {
    asm volatile("ldmatrix.sync.aligned.m8n8.x4.shared.b16 {%0,%1,%2,%3}, [%4];"
                 : "=r"(r[0]), "=r"(r[1]), "=r"(r[2]), "=r"(r[3]) : "r"(a));
}
__device__ __forceinline__ void ldsm_x2(uint32_t* r, uint32_t a) {
    asm volatile("ldmatrix.sync.aligned.m8n8.x2.shared.b16 {%0,%1}, [%2];"
                 : "=r"(r[0]), "=r"(r[1]) : "r"(a));
}
__device__ __forceinline__ void mma168(float* c, const uint32_t* a, const uint32_t* b) {
    asm volatile(
        "mma.sync.aligned.m16n8k16.row.col.f32.f16.f16.f32 "
        "{%0,%1,%2,%3}, {%4,%5,%6,%7}, {%8,%9}, {%0,%1,%2,%3};"
        : "+f"(c[0]), "+f"(c[1]), "+f"(c[2]), "+f"(c[3])
        : "r"(a[0]), "r"(a[1]), "r"(a[2]), "r"(a[3]), "r"(b[0]), "r"(b[1]));
}

// monotonic float<->int encoding for atomicMax on floats
__device__ __forceinline__ int encf(float f) {
    int i = __float_as_int(f);
    return (i >= 0) ? i : (i ^ 0x7FFFFFFF);
}
__device__ __forceinline__ float decf(int i) {
    return __int_as_float((i >= 0) ? i : (i ^ 0x7FFFFFFF));
}

// ======================= kernels ===========================================

// ---- split fp32 -> fp16 hi + fp16 lo (~22-bit combined precision) ----
__global__ void cm_split_kernel(const float* __restrict__ x0, const float* __restrict__ x1) {
    size_t i = (size_t)blockIdx.x * 256 + threadIdx.x;   // float4 index
    const size_t NV = (size_t)NB * LL * CC / 4;
    if (i >= NV) return;
    float4 a = ((const float4*)x0)[i];
    float4 b = ((const float4*)x1)[i];
    __half ah[4], al[4], bh[4], bl[4];
    float av[4] = {a.x, a.y, a.z, a.w};
    float bv[4] = {b.x, b.y, b.z, b.w};
    #pragma unroll
    for (int j = 0; j < 4; j++) {
        ah[j] = __float2half_rn(av[j]);
        al[j] = __float2half_rn(av[j] - __half2float(ah[j]));
        bh[j] = __float2half_rn(bv[j]);
        bl[j] = __float2half_rn(bv[j] - __half2float(bh[j]));
    }
    __half2* p;
    p = (__half2*)g_x0h; p[2*i] = __halves2half2(ah[0], ah[1]); p[2*i+1] = __halves2half2(ah[2], ah[3]);
    p = (__half2*)g_x0l; p[2*i] = __halves2half2(al[0], al[1]); p[2*i+1] = __halves2half2(al[2], al[3]);
    p = (__half2*)g_x1h; p[2*i] = __halves2half2(bh[0], bh[1]); p[2*i+1] = __halves2half2(bh[2], bh[3]);
    p = (__half2*)g_x1l; p[2*i] = __halves2half2(bl[0], bl[1]); p[2*i+1] = __halves2half2(bl[2], bl[3]);
}

// ---- init accumulators ----
__global__ void cm_init_kernel() {
    int i = blockIdx.x * 256 + threadIdx.x;
    if (i < NB * LL) { g_rowsum[i] = 0.0f; g_MrowEnc[i] = encf(-CUDART_INF_F); }
    if (i < NB * SS) { g_colsum[i] = 0.0f; g_McolEnc[i] = encf(-CUDART_INF_F); }
}

// ---- stage loader: Ah|Al|Bh|Bl tiles, 2048 x 16B cp.async per stage -------
__device__ __forceinline__ void load_stage(uint32_t stb, int n, int m0, int n0,
                                           int k0, int tid) {
    const size_t abase = (size_t)(n * LL + m0) * CC + k0;
    const size_t bbase = (size_t)(n * SS + n0) * CC + k0;
    #pragma unroll
    for (int i = 0; i < 8; i++) {
        int idx = tid + i * 256;          // 0..2047
        int t   = idx >> 9;               // tile 0..3
        int v   = idx & 511;
        int row = v >> 2;                 // 0..127
        int c   = v & 3;                  // 16B chunk
        const __half* g;
        if      (t == 0) g = g_x0h + abase + (size_t)row * CC;
        else if (t == 1) g = g_x0l + abase + (size_t)row * CC;
        else if (t == 2) g = g_x1h + bbase + (size_t)row * CC;
        else             g = g_x1l + bbase + (size_t)row * CC;
        uint32_t dst = stb + (uint32_t)t * TILE_B + (uint32_t)row * (LDS_ROW * 2) + c * 16;
        cpa16(dst, g + c * 8);
    }
}

// ---- GEMM: sim = (x0 @ x1^T) * INV_SCALE via fp16x3 mma.sync,
//      fused row/col sum-of-exp epilogue; 2 CTAs/SM ------------------------
__global__ void __launch_bounds__(256, 2)
cm_gemm_hmma() {
    extern __shared__ char sm[];
    uint32_t sb = smem_u32(sm);
    const int tid = threadIdx.x, lane = tid & 31, wid = tid >> 5;
    const int wm = wid & 1;           // 0..1 : 64-row half
    const int wn = wid >> 1;          // 0..3 : 32-col quarter
    const int n  = blockIdx.z;
    const int m0 = blockIdx.y * BM;
    const int n0 = blockIdx.x * BN;

    float cacc[4][4][4];
    #pragma unroll
    for (int fm = 0; fm < 4; fm++)
        #pragma unroll
        for (int fn = 0; fn < 4; fn++)
            #pragma unroll
            for (int q = 0; q < 4; q++) cacc[fm][fn][q] = 0.0f;

    // prologue: stage 0
    load_stage(sb, n, m0, n0, 0, tid);
    asm volatile("cp.async.commit_group;");

    const uint32_t a_row = (uint32_t)((lane & 15) * (LDS_ROW * 2));
    const uint32_t a_kof = (lane & 16) ? 16u : 0u;     // +8 halves
    const uint32_t b_row = (uint32_t)((lane & 7) * (LDS_ROW * 2));
    const uint32_t b_kof = (lane & 8) ? 16u : 0u;

    for (int it = 0; it < NIT; it++) {
        if (it + 1 < NIT) {
            load_stage(sb + ((it + 1) & 1) * ST_STRIDE, n, m0, n0, (it + 1) * BKH, tid);
            asm volatile("cp.async.commit_group;");
            asm volatile("cp.async.wait_group 1;");
        } else {
            asm volatile("cp.async.wait_group 0;");
        }
        __syncthreads();

        uint32_t st = sb + (it & 1) * ST_STRIDE;
        #pragma unroll
        for (int ks = 0; ks < 2; ks++) {
            uint32_t kbyte = (uint32_t)(ks * 32);   // 16 halves
            uint32_t bh[4][2], bl[4][2];
            #pragma unroll
            for (int fn = 0; fn < 4; fn++) {
                uint32_t off = (uint32_t)((wn * 32 + fn * 8) * (LDS_ROW * 2)) + b_row + kbyte + b_kof;
                ldsm_x2(bh[fn], st + BH_O + off);
                ldsm_x2(bl[fn], st + BL_O + off);
            }
            #pragma unroll
            for (int fm = 0; fm < 4; fm++) {
                uint32_t ah[4], al[4];
                uint32_t off = (uint32_t)((wm * 64 + fm * 16) * (LDS_ROW * 2)) + a_row + kbyte + a_kof;
                ldsm_x4(ah, st + AH_O + off);
                ldsm_x4(al, st + AL_O + off);
                #pragma unroll
                for (int fn = 0; fn < 4; fn++) {
                    mma168(cacc[fm][fn], ah, bh[fn]);
                    mma168(cacc[fm][fn], ah, bl[fn]);
                    mma168(cacc[fm][fn], al, bh[fn]);
                }
            }
        }
        __syncthreads();
    }

    // ---- epilogue: scale + store sim, fused exp-sum reduction ----
    float* outb = g_sim + (size_t)n * LL * SS;
    #pragma unroll
    for (int fm = 0; fm < 4; fm++) {
        int r = m0 + wm * 64 + fm * 16 + (lane >> 2);
        #pragma unroll
        for (int fn = 0; fn < 4; fn++) {
            #pragma unroll
            for (int q = 0; q < 4; q++) cacc[fm][fn][q] *= INV_SCALE;
            int cc0 = n0 + wn * 32 + fn * 8 + (lane & 3) * 2;
            *(float2*)(outb + (size_t)r * SS + cc0)       = make_float2(cacc[fm][fn][0], cacc[fm][fn][1]);
            *(float2*)(outb + (size_t)(r + 8) * SS + cc0) = make_float2(cacc[fm][fn][2], cacc[fm][fn][3]);
        }
    }

    // stage smem is dead now: alias row/col partial buffers onto it
    float* s_row = (float*)sm;          // 128 floats
    float* s_col = s_row + 128;         // 128 floats
    if (tid < 128) s_row[tid] = 0.0f; else s_col[tid - 128] = 0.0f;
    __syncthreads();

    float cp[8];
    #pragma unroll
    for (int k = 0; k < 8; k++) cp[k] = 0.0f;
    #pragma unroll
    for (int fm = 0; fm < 4; fm++) {
        float rp0 = 0.0f, rp1 = 0.0f;
        #pragma unroll
        for (int fn = 0; fn < 4; fn++) {
            float e0 = __expf(cacc[fm][fn][0]);
            float e1 = __expf(cacc[fm][fn][1]);
            float e2 = __expf(cacc[fm][fn][2]);
            float e3 = __expf(cacc[fm][fn][3]);
            rp0 += e0 + e1;
            rp1 += e2 + e3;
            cp[fn * 2]     += e0 + e2;
            cp[fn * 2 + 1] += e1 + e3;
        }
        rp0 += __shfl_xor_sync(0xffffffffu, rp0, 1);
        rp0 += __shfl_xor_sync(0xffffffffu, rp0, 2);
        rp1 += __shfl_xor_sync(0xffffffffu, rp1, 1);
        rp1 += __shfl_xor_sync(0xffffffffu, rp1, 2);
        if ((lane & 3) == 0) {
            int rl = wm * 64 + fm * 16 + (lane >> 2);
            atomicAdd(&s_row[rl], rp0);
            atomicAdd(&s_row[rl + 8], rp1);
        }
    }
    #pragma unroll
    for (int k = 0; k < 8; k++) {
        cp[k] += __shfl_xor_sync(0xffffffffu, cp[k], 4);
        cp[k] += __shfl_xor_sync(0xffffffffu, cp[k], 8);
        cp[k] += __shfl_xor_sync(0xffffffffu, cp[k], 16);
    }
    if (lane < 4) {
        #pragma unroll
        for (int k = 0; k < 8; k++) {
            int cl = wn * 32 + (k >> 1) * 8 + lane * 2 + (k & 1);
            atomicAdd(&s_col[cl], cp[k]);
        }
    }
    __syncthreads();
    if (tid < 128) atomicAdd(&g_rowsum[n * LL + m0 + tid], s_row[tid]);
    else           atomicAdd(&g_colsum[n * SS + n0 + tid - 128], s_col[tid - 128]);
}

__global__ void cm_logab_kernel() {
    int i = blockIdx.x * 256 + threadIdx.x;
    if (i < NB * LL) g_A[i] = __logf(g_rowsum[i]);
    if (i < NB * SS) g_B[i] = __logf(g_colsum[i]);
}

// ---- fused row-max of t=2sim-B[s] and col-max of u=2sim-A[l] (one read) ---
__global__ void __launch_bounds__(256) cm_maxes_kernel() {
    int n  = blockIdx.z;
    int c0 = blockIdx.x * 256;
    int r0 = blockIdx.y * 256;
    int tid = threadIdx.x, wid = tid >> 5, lid = tid & 31;
    __shared__ int cmx[256];
    __shared__ int rmx[256];
    cmx[tid] = encf(-CUDART_INF_F);
    rmx[tid] = encf(-CUDART_INF_F);
    __syncthreads();
    const float* base = g_sim + (size_t)n * LL * SS;
    const float* Ab = g_A + n * LL;
    const float4* B4 = (const float4*)(g_B + n * SS + c0);
    float4 bb0 = B4[lid];
    float4 bb1 = B4[32 + lid];
    float uacc[8];
    #pragma unroll
    for (int k = 0; k < 8; k++) uacc[k] = -CUDART_INF_F;
    for (int i = 0; i < 32; i++) {
        int r = r0 + wid + i * 8;
        float Ar = Ab[r];
        const float4* p = (const float4*)(base + (size_t)r * SS + c0);
        float4 v0 = p[lid];
        float4 v1 = p[32 + lid];
        // col max: u = 2*sim - A[l]
        uacc[0] = fmaxf(uacc[0], fmaf(2.0f, v0.x, -Ar));
        uacc[1] = fmaxf(uacc[1], fmaf(2.0f, v0.y, -Ar));
        uacc[2] = fmaxf(uacc[2], fmaf(2.0f, v0.z, -Ar));
        uacc[3] = fmaxf(uacc[3], fmaf(2.0f, v0.w, -Ar));
        uacc[4] = fmaxf(uacc[4], fmaf(2.0f, v1.x, -Ar));
        uacc[5] = fmaxf(uacc[5], fmaf(2.0f, v1.y, -Ar));
        uacc[6] = fmaxf(uacc[6], fmaf(2.0f, v1.z, -Ar));
        uacc[7] = fmaxf(uacc[7], fmaf(2.0f, v1.w, -Ar));
        // row max: t = 2*sim - B[s]
        float t = fmaxf(fmaxf(fmaf(2.0f, v0.x, -bb0.x), fmaf(2.0f, v0.y, -bb0.y)),
                        fmaxf(fmaf(2.0f, v0.z, -bb0.z), fmaf(2.0f, v0.w, -bb0.w)));
        t = fmaxf(t, fmaxf(fmaxf(fmaf(2.0f, v1.x, -bb1.x), fmaf(2.0f, v1.y, -bb1.y)),
                           fmaxf(fmaf(2.0f, v1.z, -bb1.z), fmaf(2.0f, v1.w, -bb1.w))));
        #pragma unroll
        for (int o = 16; o; o >>= 1) t = fmaxf(t, __shfl_xor_sync(0xffffffffu, t, o));
        if (lid == 0) rmx[wid + i * 8] = max(rmx[wid + i * 8], encf(t));
    }
    #pragma unroll
    for (int k = 0; k < 4; k++) {
        atomicMax(&cmx[lid * 4 + k], encf(uacc[k]));
        atomicMax(&cmx[128 + lid * 4 + k], encf(uacc[4 + k]));
    }
    __syncthreads();
    atomicMax(&g_McolEnc[n * SS + c0 + tid], cmx[tid]);
    atomicMax(&g_MrowEnc[n * LL + r0 + tid], rmx[tid]);
}

// ---- final: single sweep -> confidence, mask, scores ----------------------
__global__ void __launch_bounds__(256) cm_final_kernel(float* __restrict__ out) {
    const size_t NLS = (size_t)NB * LL * SS;
    int row = blockIdx.x;
    int n = row / LL;
    int l = row - n * LL;
    int ih = l / WW, iw = l - ih * WW;
    bool lvalid = (ih >= BORD) && (ih < HH - BORD) && (iw >= BORD) && (iw < WW - BORD);
    float Av = g_A[row];
    float Mr = decf(g_MrowEnc[row]);
    const float* p  = g_sim + (size_t)row * SS;
    const float* Bp = g_B + n * SS;
    const int* McE  = g_McolEnc + n * SS;
    float* conf_out = out + (size_t)row * SS;
    float* mask_out = out + NLS + (size_t)row * SS;
    float* scor_out = out + 2 * NLS + (size_t)row * SS;

    for (int i4 = threadIdx.x; i4 < SS / 4; i4 += 256) {
        int s = i4 * 4;
        float4 sv = *(const float4*)(p + s);
        float4 bv = *(const float4*)(Bp + s);
        float vv[4] = {sv.x, sv.y, sv.z, sv.w};
        float bb[4] = {bv.x, bv.y, bv.z, bv.w};
        float co[4], mo[4], so[4];
        #pragma unroll
        for (int j = 0; j < 4; j++) {
            int sc = s + j;
            int sh = sc / WW, sw = sc - sh * WW;
            bool svalid = (sh >= BORD) && (sh < HH - BORD) && (sw >= BORD) && (sw < WW - BORD);
            float t = fmaf(2.0f, vv[j], -bb[j]);   // identical expr to maxes pass
            float u = fmaf(2.0f, vv[j], -Av);      // identical expr to maxes pass
            float cf = __expf(t - Av);             // conf = exp(2*sim - A - B)
            bool mk = (cf > THRESH) && lvalid && svalid &&
                      (t == Mr) && (u == decf(McE[sc]));
            co[j] = cf;
            mo[j] = mk ? 1.0f : 0.0f;
            so[j] = mk ? cf : 0.0f;
        }
        *(float4*)(conf_out + s) = make_float4(co[0], co[1], co[2], co[3]);
        *(float4*)(mask_out + s) = make_float4(mo[0], mo[1], mo[2], mo[3]);
        *(float4*)(scor_out + s) = make_float4(so[0], so[1], so[2], so[3]);
    }
}

// ---- launch ----------------------------------------------------------------
extern "C" void kernel_launch(void* const* d_in, const int* in_sizes, int n_in,
                              void* d_out, int out_size) {
    const float* x0 = (const float*)d_in[0];
    const float* x1 = (const float*)d_in[1];
    float* out = (float*)d_out;

    cudaFuncSetAttribute(cm_gemm_hmma, cudaFuncAttributeMaxDynamicSharedMemorySize, SMEM_TOTAL);

    cm_split_kernel<<<(NB * LL * CC / 4 + 255) / 256, 256>>>(x0, x1);
    cm_init_kernel<<<(NB * SS + 255) / 256, 256>>>();

    dim3 gg(SS / BN, LL / BM, NB);      // (50, 50, 2)
    cm_gemm_hmma<<<gg, 256, SMEM_TOTAL>>>();

    cm_logab_kernel<<<(NB * SS + 255) / 256, 256>>>();

    dim3 gs(SS / 256, LL / 256, NB);    // (25, 25, 2)
    cm_maxes_kernel<<<gs, 256>>>();

    cm_final_kernel<<<NB * LL, 256>>>(out);
}